// round 16
// baseline (speedup 1.0000x reference)
#include <cuda_runtime.h>
#include <cuda_bf16.h>
#include <cstdint>

// Problem constants (Query2Context_15539191677614)
#define T_LEN 16384
#define J_LEN 64
#define D_LEN 1024
#define NB    296            // blocks, 2/SM on 148 SMs -> all co-resident
#define NW    148            // P2 writer blocks (rest are readers)
#define COLH  512            // column half (floats)
#define COLH4 128            // column half (float4)

// Scratch (no cudaMalloc; overwritten every replay -> deterministic)
__device__ float g_e[T_LEN];                 // exp(rowmax)
__device__ float g_bsum[NB];                 // per-P1-block exp sums
__device__ float g_partialA[NB * COLH];      // k in [0,512)
__device__ float g_partialB[NW * COLH];      // k in [512,1024)

// Monotonic grid barrier (never reset; replay-safe) — R8-proven pattern
__device__ unsigned g_ticket  = 0;
__device__ unsigned g_release = 0;

__device__ __forceinline__ void grid_barrier(int tid) {
    __threadfence();
    __syncthreads();
    if (tid == 0) {
        volatile unsigned* rel = &g_release;
        const unsigned gen = *rel;              // read BEFORE arriving
        const unsigned t = atomicAdd(&g_ticket, 1);
        if ((t % NB) == (NB - 1)) {
            atomicAdd(&g_release, 1);
        } else {
            while (*rel == gen) { }
        }
    }
    __syncthreads();
    __threadfence();
}

// Reduce over sh[0..511]. ALL 1024 threads must call (syncs inside).
// Only tids < 512 touch the array; returns sh[0] to every thread.
__device__ __forceinline__ float reduce512(float* sh, int tid) {
    #pragma unroll
    for (int off = 256; off > 0; off >>= 1) {
        if (tid < off) sh[tid] += sh[tid + off];
        __syncthreads();
    }
    return sh[0];
}

// ---------------------------------------------------------------------------
__global__ __launch_bounds__(1024, 2)
void k_all(const float* __restrict__ h, const float* __restrict__ s,
           float* __restrict__ out) {
    __shared__ float  e_sh[112];          // P1: <=56 rows; P2 reader: <=111
    __shared__ __align__(16) float4 red[8][COLH4];   // 16KB
    __shared__ float  shp[512];
    __shared__ float  shs[512];

    const int b    = blockIdx.x;
    const int tid  = threadIdx.x;
    const int w    = tid >> 5;
    const int lane = tid & 31;
    const int g    = tid >> 7;            // row-group 0..7
    const int c4   = tid & 127;           // float4 col within a 512-col half
    const float* redf = reinterpret_cast<const float*>(red);

    // ======================= PHASE 1 =======================
    {
        const int t0    = (int)(((long long)b       * T_LEN) / NB);
        const int t1    = (int)(((long long)(b + 1) * T_LEN) / NB);
        const int nrows = t1 - t0;        // 55 or 56

        // rowmax/exp: warp-per-row (lane reads float2 of s)
        for (int r = w; r < nrows; r += 32) {
            const float2 v = __ldcs(reinterpret_cast<const float2*>(
                s + (size_t)(t0 + r) * J_LEN) + lane);
            float m = fmaxf(v.x, v.y);
            #pragma unroll
            for (int off = 16; off > 0; off >>= 1)
                m = fmaxf(m, __shfl_xor_sync(0xFFFFFFFFu, m, off));
            if (lane == 0) e_sh[r] = expf(m);
        }
        __syncthreads();

        // spill e + block exp-sum
        if (tid < nrows) g_e[t0 + tid] = e_sh[tid];
        if (w == 0) {
            float bs = 0.0f;
            for (int r = lane; r < nrows; r += 32) bs += e_sh[r];
            #pragma unroll
            for (int off = 16; off > 0; off >>= 1)
                bs += __shfl_xor_sync(0xFFFFFFFFu, bs, off);
            if (lane == 0) g_bsum[b] = bs;
        }

        // stream h[:, 0:512]: 8 rows per iteration
        float4 acc = make_float4(0.f, 0.f, 0.f, 0.f);
        const float4* __restrict__ hp =
            reinterpret_cast<const float4*>(h) + (size_t)t0 * 256 + c4;
        const int ni = (nrows + 7) >> 3;
        for (int i = 0; i < ni; i++) {
            const int rl = i * 8 + g;
            if (rl < nrows) {
                const float4 v = __ldcs(hp + (size_t)rl * 256);
                const float  e = e_sh[rl];
                acc.x = fmaf(e, v.x, acc.x);
                acc.y = fmaf(e, v.y, acc.y);
                acc.z = fmaf(e, v.z, acc.z);
                acc.w = fmaf(e, v.w, acc.w);
            }
        }
        red[g][c4] = acc;
        __syncthreads();
        if (tid < COLH) {
            float v = 0.0f;
            #pragma unroll
            for (int gg = 0; gg < 8; gg++) v += redf[gg * 512 + tid];
            g_partialA[(size_t)b * COLH + tid] = v;
        }
        __syncthreads();
    }

    grid_barrier(tid);

    // ======================= PHASE 2 =======================
    if (b < NW) {
        // -------- WRITER: output rows [b*512/NW, (b+1)*512/NW) --------
        const int k0 = (b * COLH) / NW;
        const int k1 = ((b + 1) * COLH) / NW;     // 3-4 rows

        if (tid < 512) shs[tid] = (tid < NB) ? g_bsum[tid] : 0.0f;
        __syncthreads();
        const float S = reduce512(shs, tid);

        for (int k = k0; k < k1; k++) {
            if (tid < 512)
                shp[tid] = (tid < NB) ? g_partialA[(size_t)tid * COLH + k] : 0.0f;
            __syncthreads();
            const float ctx = reduce512(shp, tid);
            const float v = ctx / S;
            const float4 vv = make_float4(v, v, v, v);
            float4* __restrict__ row =
                reinterpret_cast<float4*>(out) + (size_t)k * (T_LEN / 4);
            #pragma unroll
            for (int j = 0; j < 4; j++)
                __stcs(row + j * 1024 + tid, vv);
            __syncthreads();              // protect shp reuse next iter
        }
    } else {
        // -------- READER: h[:, 512:1024) for rows [ri*T/NW, ...) --------
        const int ri    = b - NW;
        const int t0    = (int)(((long long)ri       * T_LEN) / NW);
        const int t1    = (int)(((long long)(ri + 1) * T_LEN) / NW);
        const int nrows = t1 - t0;        // 110 or 111

        for (int r = tid; r < nrows; r += 1024) e_sh[r] = g_e[t0 + r];
        __syncthreads();

        float4 acc = make_float4(0.f, 0.f, 0.f, 0.f);
        const float4* __restrict__ hp =
            reinterpret_cast<const float4*>(h) + (size_t)t0 * 256 + 128 + c4;
        const int ni = (nrows + 7) >> 3;
        for (int i = 0; i < ni; i++) {
            const int rl = i * 8 + g;
            if (rl < nrows) {
                const float4 v = __ldcs(hp + (size_t)rl * 256);
                const float  e = e_sh[rl];
                acc.x = fmaf(e, v.x, acc.x);
                acc.y = fmaf(e, v.y, acc.y);
                acc.z = fmaf(e, v.z, acc.z);
                acc.w = fmaf(e, v.w, acc.w);
            }
        }
        red[g][c4] = acc;
        __syncthreads();
        if (tid < COLH) {
            float v = 0.0f;
            #pragma unroll
            for (int gg = 0; gg < 8; gg++) v += redf[gg * 512 + tid];
            g_partialB[(size_t)ri * COLH + tid] = v;
        }
        __syncthreads();
    }

    grid_barrier(tid);

    // ======================= PHASE 3 =======================
    {
        const int k0 = (b * COLH) / NB;
        const int k1 = ((b + 1) * COLH) / NB;     // 1-2 rows

        if (tid < 512) shs[tid] = (tid < NB) ? g_bsum[tid] : 0.0f;
        __syncthreads();
        const float S = reduce512(shs, tid);

        for (int kk = k0; kk < k1; kk++) {
            if (tid < 512)
                shp[tid] = (tid < NW) ? g_partialB[(size_t)tid * COLH + kk] : 0.0f;
            __syncthreads();
            const float ctx = reduce512(shp, tid);
            const float v = ctx / S;
            const float4 vv = make_float4(v, v, v, v);
            float4* __restrict__ row =
                reinterpret_cast<float4*>(out) + (size_t)(COLH + kk) * (T_LEN / 4);
            #pragma unroll
            for (int j = 0; j < 4; j++)
                __stcs(row + j * 1024 + tid, vv);
            __syncthreads();              // protect shp reuse next iter
        }
    }
}

// ---------------------------------------------------------------------------
extern "C" void kernel_launch(void* const* d_in, const int* in_sizes, int n_in,
                              void* d_out, int out_size) {
    const float* h = (const float*)d_in[0];   // [1, T, d]
    const float* s = (const float*)d_in[1];   // [T, J]
    float* out = (float*)d_out;               // [d, T]

    k_all<<<NB, 1024>>>(h, s, out);
}